// round 3
// baseline (speedup 1.0000x reference)
#include <cuda_runtime.h>
#include <math.h>

// SparseMoE: T=2048 tokens, D=1024, F=4096, E=8, top-2 routing.
// Pipeline: router (top-2 + softmax gates) -> per-expert token gather ->
// grouped GEMM1 (x @ W1_e, +b1, ReLU) -> grouped GEMM2 (h @ W2_e, +b2, *gate)
// -> combine (sum of the 2 expert outputs per token).

#define D_DIM 1024
#define E_NUM 8
#define F_DIM 4096
#define MAXT  2048
#define MAXROWS (2 * MAXT)

// Scratch (device globals; no cudaMalloc allowed).
__device__ float g_h[(size_t)MAXROWS * F_DIM];   // 67 MB: post-ReLU activations per slot
__device__ float g_y[(size_t)MAXROWS * D_DIM];   // 16.8 MB: gated expert outputs per slot
__device__ int   g_cnt[E_NUM];
__device__ int   g_off[E_NUM];
__device__ int   g_topi[MAXT * 2];
__device__ float g_gate[MAXT * 2];
__device__ int   g_pos[MAXT * 2];
__device__ int   g_slot[MAXT * 2];
__device__ int   g_rowtok[MAXROWS];
__device__ float g_rowgate[MAXROWS];

__global__ void zero_cnt_kernel() {
    if (threadIdx.x < E_NUM) g_cnt[threadIdx.x] = 0;
}

// One warp per token: logits = x_t @ Wn + bn, top-2, softmax over the 2 values.
__global__ void router_kernel(const float* __restrict__ x,
                              const float* __restrict__ Wn,
                              const float* __restrict__ bn, int T) {
    int gw   = (blockIdx.x * blockDim.x + threadIdx.x) >> 5;
    int lane = threadIdx.x & 31;
    if (gw >= T) return;
    const float* xr = x + (size_t)gw * D_DIM;

    float acc[E_NUM];
#pragma unroll
    for (int e = 0; e < E_NUM; e++) acc[e] = 0.f;

    for (int d = lane; d < D_DIM; d += 32) {
        float xv = xr[d];
#pragma unroll
        for (int e = 0; e < E_NUM; e++) acc[e] += xv * Wn[d * E_NUM + e];
    }
#pragma unroll
    for (int off = 16; off; off >>= 1) {
#pragma unroll
        for (int e = 0; e < E_NUM; e++)
            acc[e] += __shfl_xor_sync(0xffffffffu, acc[e], off);
    }

    if (lane == 0) {
        float v[E_NUM];
#pragma unroll
        for (int e = 0; e < E_NUM; e++) v[e] = acc[e] + bn[e];
        // top-1 (strict > : lowest index wins ties, matching jax top_k)
        int i0 = 0;
#pragma unroll
        for (int e = 1; e < E_NUM; e++) if (v[e] > v[i0]) i0 = e;
        int i1 = (i0 == 0) ? 1 : 0;
#pragma unroll
        for (int e = 0; e < E_NUM; e++)
            if (e != i0 && v[e] > v[i1]) i1 = e;

        float ex = expf(v[i1] - v[i0]);     // <= 1
        float g0 = 1.f / (1.f + ex);
        float g1 = ex / (1.f + ex);

        int p0 = atomicAdd(&g_cnt[i0], 1);
        int p1 = atomicAdd(&g_cnt[i1], 1);
        int b = gw * 2;
        g_topi[b]     = i0;  g_topi[b + 1] = i1;
        g_gate[b]     = g0;  g_gate[b + 1] = g1;
        g_pos[b]      = p0;  g_pos[b + 1]  = p1;
    }
}

__global__ void scan_kernel() {
    if (threadIdx.x == 0) {
        int s = 0;
        for (int e = 0; e < E_NUM; e++) { g_off[e] = s; s += g_cnt[e]; }
    }
}

__global__ void build_kernel(int T) {
    int i = blockIdx.x * blockDim.x + threadIdx.x;
    if (i >= T * 2) return;
    int e    = g_topi[i];
    int slot = g_off[e] + g_pos[i];
    g_slot[i]       = slot;
    g_rowtok[slot]  = i >> 1;
    g_rowgate[slot] = g_gate[i];
}

// ---------------- 128x128 tile SGEMM cores (BK=8, 256 thr, 8x8/thread) ----

// GEMM1: h[slot, n] = relu( x[tok(slot), :] @ W1[e][:, n] + b1[e][n] )
__global__ __launch_bounds__(256)
void ffn1_kernel(const float* __restrict__ x,
                 const float* __restrict__ W1,
                 const float* __restrict__ b1) {
    const int e   = blockIdx.z;
    const int cnt = g_cnt[e];
    const int m0  = blockIdx.y * 128;
    if (m0 >= cnt) return;
    const int base = g_off[e];
    const int n0   = blockIdx.x * 128;
    const int tid  = threadIdx.x;

    __shared__ float As[8][128];
    __shared__ float Bs[8][128];

    // A load assignment: 2 threads per row, float4 each
    const int arow = tid >> 1;
    const int ak   = (tid & 1) * 4;
    int gm   = m0 + arow;
    int asrc = base + ((gm < cnt) ? gm : (cnt - 1));
    const float* aptr = x + (size_t)g_rowtok[asrc] * D_DIM + ak;

    // B load assignment: 32 threads per row (128 floats), float4 each
    const int brow = tid >> 5;
    const int bcol = (tid & 31) * 4;
    const float* bptr = W1 + (size_t)e * D_DIM * F_DIM + (size_t)brow * F_DIM + n0 + bcol;

    const int rm = (tid >> 4) * 4;   // rows {rm..rm+3, rm+64..rm+67}
    const int cn = (tid & 15) * 4;   // cols {cn..cn+3, cn+64..cn+67}

    float acc[8][8];
#pragma unroll
    for (int i = 0; i < 8; i++)
#pragma unroll
        for (int j = 0; j < 8; j++) acc[i][j] = 0.f;

    for (int k0 = 0; k0 < D_DIM; k0 += 8) {
        float4 av = *(const float4*)(aptr + k0);
        float4 bv = *(const float4*)(bptr);
        bptr += 8 * F_DIM;
        __syncthreads();
        As[ak + 0][arow] = av.x; As[ak + 1][arow] = av.y;
        As[ak + 2][arow] = av.z; As[ak + 3][arow] = av.w;
        *(float4*)&Bs[brow][bcol] = bv;
        __syncthreads();
#pragma unroll
        for (int kk = 0; kk < 8; kk++) {
            float a[8], b[8];
            *(float4*)&a[0] = *(const float4*)&As[kk][rm];
            *(float4*)&a[4] = *(const float4*)&As[kk][rm + 64];
            *(float4*)&b[0] = *(const float4*)&Bs[kk][cn];
            *(float4*)&b[4] = *(const float4*)&Bs[kk][cn + 64];
#pragma unroll
            for (int i = 0; i < 8; i++)
#pragma unroll
                for (int j = 0; j < 8; j++) acc[i][j] += a[i] * b[j];
        }
    }

#pragma unroll
    for (int i = 0; i < 8; i++) {
        int r   = (i < 4) ? (rm + i) : (rm + 60 + i);
        int gmr = m0 + r;
        if (gmr >= cnt) continue;
        size_t orow = (size_t)(base + gmr) * F_DIM + n0;
#pragma unroll
        for (int j = 0; j < 8; j++) {
            int c = (j < 4) ? (cn + j) : (cn + 60 + j);
            float hv = acc[i][j] + b1[e * F_DIM + n0 + c];
            g_h[orow + c] = hv > 0.f ? hv : 0.f;
        }
    }
}

// GEMM2: y[slot, n] = gate(slot) * ( h[slot, :] @ W2[e][:, n] + b2[e][n] )
__global__ __launch_bounds__(256)
void ffn2_kernel(const float* __restrict__ W2,
                 const float* __restrict__ b2) {
    const int e   = blockIdx.z;
    const int cnt = g_cnt[e];
    const int m0  = blockIdx.y * 128;
    if (m0 >= cnt) return;
    const int base = g_off[e];
    const int n0   = blockIdx.x * 128;
    const int tid  = threadIdx.x;

    __shared__ float As[8][128];
    __shared__ float Bs[8][128];

    const int arow = tid >> 1;
    const int ak   = (tid & 1) * 4;
    int gm  = m0 + arow;
    int row = base + ((gm < cnt) ? gm : (cnt - 1));
    const float* aptr = g_h + (size_t)row * F_DIM + ak;

    const int brow = tid >> 5;
    const int bcol = (tid & 31) * 4;
    const float* bptr = W2 + (size_t)e * F_DIM * D_DIM + (size_t)brow * D_DIM + n0 + bcol;

    const int rm = (tid >> 4) * 4;
    const int cn = (tid & 15) * 4;

    float acc[8][8];
#pragma unroll
    for (int i = 0; i < 8; i++)
#pragma unroll
        for (int j = 0; j < 8; j++) acc[i][j] = 0.f;

    for (int k0 = 0; k0 < F_DIM; k0 += 8) {
        float4 av = *(const float4*)(aptr + k0);
        float4 bv = *(const float4*)(bptr);
        bptr += 8 * D_DIM;
        __syncthreads();
        As[ak + 0][arow] = av.x; As[ak + 1][arow] = av.y;
        As[ak + 2][arow] = av.z; As[ak + 3][arow] = av.w;
        *(float4*)&Bs[brow][bcol] = bv;
        __syncthreads();
#pragma unroll
        for (int kk = 0; kk < 8; kk++) {
            float a[8], b[8];
            *(float4*)&a[0] = *(const float4*)&As[kk][rm];
            *(float4*)&a[4] = *(const float4*)&As[kk][rm + 64];
            *(float4*)&b[0] = *(const float4*)&Bs[kk][cn];
            *(float4*)&b[4] = *(const float4*)&Bs[kk][cn + 64];
#pragma unroll
            for (int i = 0; i < 8; i++)
#pragma unroll
                for (int j = 0; j < 8; j++) acc[i][j] += a[i] * b[j];
        }
    }

#pragma unroll
    for (int i = 0; i < 8; i++) {
        int r   = (i < 4) ? (rm + i) : (rm + 60 + i);
        int gmr = m0 + r;
        if (gmr >= cnt) continue;
        float gate  = g_rowgate[base + gmr];
        size_t orow = (size_t)(base + gmr) * D_DIM + n0;
#pragma unroll
        for (int j = 0; j < 8; j++) {
            int c = (j < 4) ? (cn + j) : (cn + 60 + j);
            g_y[orow + c] = gate * (acc[i][j] + b2[e * D_DIM + n0 + c]);
        }
    }
}

__global__ void combine_kernel(float* __restrict__ out, int T) {
    int i = blockIdx.x * blockDim.x + threadIdx.x;
    if (i >= T * D_DIM) return;
    int t = i >> 10;           // / D_DIM
    int d = i & (D_DIM - 1);   // % D_DIM
    out[i] = g_y[(size_t)g_slot[t * 2] * D_DIM + d] +
             g_y[(size_t)g_slot[t * 2 + 1] * D_DIM + d];
}

extern "C" void kernel_launch(void* const* d_in, const int* in_sizes, int n_in,
                              void* d_out, int out_size) {
    const float* x  = (const float*)d_in[0];
    const float* Wn = (const float*)d_in[1];
    const float* bn = (const float*)d_in[2];
    const float* W1 = (const float*)d_in[3];
    const float* b1 = (const float*)d_in[4];
    const float* W2 = (const float*)d_in[5];
    const float* b2 = (const float*)d_in[6];
    const int T = in_sizes[0] / D_DIM;

    zero_cnt_kernel<<<1, 32>>>();
    router_kernel<<<(T * 32 + 255) / 256, 256>>>(x, Wn, bn, T);
    scan_kernel<<<1, 32>>>();
    build_kernel<<<(T * 2 + 255) / 256, 256>>>(T);

    const int MT = (T + 127) / 128;   // worst case: one expert gets all tokens
    dim3 g1(F_DIM / 128, MT, E_NUM);
    ffn1_kernel<<<g1, 256>>>(x, W1, b1);
    dim3 g2(D_DIM / 128, MT, E_NUM);
    ffn2_kernel<<<g2, 256>>>(W2, b2);

    combine_kernel<<<(T * D_DIM + 255) / 256, 256>>>((float*)d_out, T);
}

// round 5
// speedup vs baseline: 2.3762x; 2.3762x over previous
#include <cuda_runtime.h>
#include <cuda_bf16.h>
#include <math.h>
#include <stdint.h>

// SparseMoE: T=2048, D=1024, F=4096, E=8, top-2.
// router -> convert weights to bf16 hi/lo planes (once per launch) ->
// gather+convert tokens -> grouped GEMM1 (bf16x3 mma.sync, relu, writes bf16
// hi/lo h planes) -> grouped GEMM2 (bf16x3, gate) -> combine.

#define D_DIM 1024
#define E_NUM 8
#define F_DIM 4096
#define MAXT  2048
#define MAXROWS (2 * MAXT)

// -------------------- device scratch (no cudaMalloc allowed) ---------------
__device__ __nv_bfloat16 g_w1h[(size_t)E_NUM * D_DIM * F_DIM];
__device__ __nv_bfloat16 g_w1l[(size_t)E_NUM * D_DIM * F_DIM];
__device__ __nv_bfloat16 g_w2h[(size_t)E_NUM * F_DIM * D_DIM];
__device__ __nv_bfloat16 g_w2l[(size_t)E_NUM * F_DIM * D_DIM];
__device__ __nv_bfloat16 g_xh[(size_t)MAXROWS * D_DIM];
__device__ __nv_bfloat16 g_xl[(size_t)MAXROWS * D_DIM];
__device__ __nv_bfloat16 g_hh[(size_t)MAXROWS * F_DIM];
__device__ __nv_bfloat16 g_hl[(size_t)MAXROWS * F_DIM];
__device__ float g_y[(size_t)MAXROWS * D_DIM];
__device__ int   g_cnt[E_NUM];
__device__ int   g_off[E_NUM];
__device__ int   g_topi[MAXT * 2];
__device__ float g_gate[MAXT * 2];
__device__ int   g_pos[MAXT * 2];
__device__ int   g_slot[MAXT * 2];
__device__ int   g_rowtok[MAXROWS];
__device__ float g_rowgate[MAXROWS];

// -------------------- helpers ----------------------------------------------
__device__ __forceinline__ uint32_t smem_u32(const void* p) {
    uint32_t a;
    asm("{ .reg .u64 t; cvta.to.shared.u64 t, %1; cvt.u32.u64 %0, t; }"
        : "=r"(a) : "l"(p));
    return a;
}

#define SW128(o) ((uint32_t)(o) ^ ((((uint32_t)(o)) >> 3) & 0x70u))

#define CPASYNC16(s, g) \
    asm volatile("cp.async.cg.shared.global [%0], [%1], 16;" \
        :: "r"((uint32_t)(s)), "l"(g) : "memory")
#define CPCOMMIT() asm volatile("cp.async.commit_group;" ::: "memory")
#define CPWAIT1()  asm volatile("cp.async.wait_group 1;" ::: "memory")
#define CPWAIT0()  asm volatile("cp.async.wait_group 0;" ::: "memory")

__device__ __forceinline__ void ldsm_x4(uint32_t* r, uint32_t addr) {
    asm volatile("ldmatrix.sync.aligned.m8n8.x4.shared.b16 {%0,%1,%2,%3}, [%4];"
        : "=r"(r[0]), "=r"(r[1]), "=r"(r[2]), "=r"(r[3]) : "r"(addr));
}
__device__ __forceinline__ void ldsm_x4_t(uint32_t* r, uint32_t addr) {
    asm volatile("ldmatrix.sync.aligned.m8n8.x4.trans.shared.b16 {%0,%1,%2,%3}, [%4];"
        : "=r"(r[0]), "=r"(r[1]), "=r"(r[2]), "=r"(r[3]) : "r"(addr));
}
__device__ __forceinline__ void mma16816(float* c, const uint32_t* a,
                                         uint32_t b0, uint32_t b1) {
    asm volatile(
        "mma.sync.aligned.m16n8k16.row.col.f32.bf16.bf16.f32 "
        "{%0,%1,%2,%3}, {%4,%5,%6,%7}, {%8,%9}, {%0,%1,%2,%3};"
        : "+f"(c[0]), "+f"(c[1]), "+f"(c[2]), "+f"(c[3])
        : "r"(a[0]), "r"(a[1]), "r"(a[2]), "r"(a[3]), "r"(b0), "r"(b1));
}

// pack two fp32 -> (hi bf16x2, lo bf16x2)
__device__ __forceinline__ uint32_t pack2(float a, float b, uint32_t& lo2) {
    __nv_bfloat16 ha = __float2bfloat16_rn(a);
    __nv_bfloat16 hb = __float2bfloat16_rn(b);
    __nv_bfloat16 la = __float2bfloat16_rn(a - __bfloat162float(ha));
    __nv_bfloat16 lb = __float2bfloat16_rn(b - __bfloat162float(hb));
    lo2 = (uint32_t)*(unsigned short*)&la | ((uint32_t)*(unsigned short*)&lb << 16);
    return (uint32_t)*(unsigned short*)&ha | ((uint32_t)*(unsigned short*)&hb << 16);
}

// -------------------- router ------------------------------------------------
__global__ void zero_cnt_kernel() {
    if (threadIdx.x < E_NUM) g_cnt[threadIdx.x] = 0;
}

__global__ void router_kernel(const float* __restrict__ x,
                              const float* __restrict__ Wn,
                              const float* __restrict__ bn, int T) {
    int gw   = (blockIdx.x * blockDim.x + threadIdx.x) >> 5;
    int lane = threadIdx.x & 31;
    if (gw >= T) return;
    const float* xr = x + (size_t)gw * D_DIM;
    float acc[E_NUM];
#pragma unroll
    for (int e = 0; e < E_NUM; e++) acc[e] = 0.f;
    for (int d = lane; d < D_DIM; d += 32) {
        float xv = xr[d];
#pragma unroll
        for (int e = 0; e < E_NUM; e++) acc[e] += xv * Wn[d * E_NUM + e];
    }
#pragma unroll
    for (int off = 16; off; off >>= 1)
#pragma unroll
        for (int e = 0; e < E_NUM; e++)
            acc[e] += __shfl_xor_sync(0xffffffffu, acc[e], off);

    if (lane == 0) {
        float v[E_NUM];
#pragma unroll
        for (int e = 0; e < E_NUM; e++) v[e] = acc[e] + bn[e];
        int i0 = 0;
#pragma unroll
        for (int e = 1; e < E_NUM; e++) if (v[e] > v[i0]) i0 = e;
        int i1 = (i0 == 0) ? 1 : 0;
#pragma unroll
        for (int e = 0; e < E_NUM; e++)
            if (e != i0 && v[e] > v[i1]) i1 = e;
        float ex = expf(v[i1] - v[i0]);
        float g0 = 1.f / (1.f + ex);
        float g1 = ex / (1.f + ex);
        int p0 = atomicAdd(&g_cnt[i0], 1);
        int p1 = atomicAdd(&g_cnt[i1], 1);
        int b = gw * 2;
        g_topi[b] = i0; g_topi[b + 1] = i1;
        g_gate[b] = g0; g_gate[b + 1] = g1;
        g_pos[b]  = p0; g_pos[b + 1]  = p1;
    }
}

__global__ void scan_kernel() {
    if (threadIdx.x == 0) {
        int s = 0;
        for (int e = 0; e < E_NUM; e++) { g_off[e] = s; s += g_cnt[e]; }
    }
}

__global__ void build_kernel(int T) {
    int i = blockIdx.x * blockDim.x + threadIdx.x;
    if (i >= T * 2) return;
    int e = g_topi[i];
    int slot = g_off[e] + g_pos[i];
    g_slot[i] = slot;
    g_rowtok[slot]  = i >> 1;
    g_rowgate[slot] = g_gate[i];
}

// -------------------- conversions ------------------------------------------
__global__ void convert_kernel(const float* __restrict__ src,
                               __nv_bfloat16* __restrict__ hi,
                               __nv_bfloat16* __restrict__ lo, size_t n4) {
    size_t i = (size_t)blockIdx.x * blockDim.x + threadIdx.x;
    if (i >= n4) return;
    float4 v = ((const float4*)src)[i];
    uint32_t l0, l1;
    uint32_t h0 = pack2(v.x, v.y, l0);
    uint32_t h1 = pack2(v.z, v.w, l1);
    ((uint2*)hi)[i] = make_uint2(h0, h1);
    ((uint2*)lo)[i] = make_uint2(l0, l1);
}

__global__ void gatherx_kernel(const float* __restrict__ x) {
    int slot = blockIdx.x;
    int d = threadIdx.x * 4;
    float4 v = *(const float4*)(x + (size_t)g_rowtok[slot] * D_DIM + d);
    uint32_t l0, l1;
    uint32_t h0 = pack2(v.x, v.y, l0);
    uint32_t h1 = pack2(v.z, v.w, l1);
    size_t o = ((size_t)slot * D_DIM + d) >> 2;
    ((uint2*)g_xh)[o] = make_uint2(h0, h1);
    ((uint2*)g_xl)[o] = make_uint2(l0, l1);
}

// -------------------- grouped GEMM (bf16x3 mma.sync) ------------------------
// C[slot, n] = epi( A[slot, :K] @ B_e[:K, n] + bias_e[n] )
// A planes: bf16 [slot][K] ; B planes: bf16 [E][K][N]
// Tile 128x128, K-chunk 64, 512 thr (16 warps, 4x4), double-buffered smem.
#define AHI_OFF 0
#define ALO_OFF 16384
#define BHI_OFF 32768
#define BLO_OFF 49152
#define STAGE_BYTES 65536
#define SMEM_DYN (2 * STAGE_BYTES)

template<int KDIM, int NDIM, bool RELU>
__global__ __launch_bounds__(512, 1)
void moe_gemm_kernel(const __nv_bfloat16* __restrict__ Ahi,
                     const __nv_bfloat16* __restrict__ Alo,
                     const __nv_bfloat16* __restrict__ Bhi,
                     const __nv_bfloat16* __restrict__ Blo,
                     const float* __restrict__ bias,
                     __nv_bfloat16* __restrict__ Chi,   // GEMM1 out (hi plane)
                     __nv_bfloat16* __restrict__ Clo,   // GEMM1 out (lo plane)
                     float* __restrict__ Cf) {          // GEMM2 out (fp32)
    const int e   = blockIdx.z;
    const int cnt = g_cnt[e];
    const int m0  = blockIdx.y * 128;
    if (m0 >= cnt) return;
    const int base = g_off[e];
    const int n0   = blockIdx.x * 128;
    const int tid  = threadIdx.x;
    const int wid  = tid >> 5;
    const int lane = tid & 31;
    const int wm   = wid & 3;    // warp row (32 rows)
    const int wn   = wid >> 2;   // warp col (32 cols)

    extern __shared__ char smem[];
    const uint32_t sb = smem_u32(smem);

    const __nv_bfloat16* Behi = Bhi + (size_t)e * KDIM * NDIM;
    const __nv_bfloat16* Belo = Blo + (size_t)e * KDIM * NDIM;

    // staging assignments (2 x 16B per plane per thread)
    size_t a_go[2], b_go[2];
    uint32_t a_sw[2], b_sw[2];
#pragma unroll
    for (int i = 0; i < 2; i++) {
        int idx = tid + i * 512;
        int ar = idx >> 3, kg = idx & 7;           // A: 128 rows x 8 chunks
        int am = m0 + ar; if (am >= cnt) am = cnt - 1;
        a_go[i] = (size_t)(base + am) * KDIM + kg * 8;
        a_sw[i] = SW128(ar * 128 + kg * 16);
        int bk = idx >> 4, bj = idx & 15;          // B: 64 k x 16 chunks
        int bh = bj >> 3, bn = bj & 7;
        b_go[i] = (size_t)bk * NDIM + n0 + bh * 64 + bn * 8;
        b_sw[i] = bh * 8192 + SW128(bk * 128 + bn * 16);
    }

    auto issue = [&](int c) {
        uint32_t st = sb + (c & 1) * STAGE_BYTES;
        const __nv_bfloat16* pah = Ahi + (size_t)c * 64;
        const __nv_bfloat16* pal = Alo + (size_t)c * 64;
        const __nv_bfloat16* pbh = Behi + (size_t)c * 64 * NDIM;
        const __nv_bfloat16* pbl = Belo + (size_t)c * 64 * NDIM;
#pragma unroll
        for (int i = 0; i < 2; i++) {
            CPASYNC16(st + AHI_OFF + a_sw[i], pah + a_go[i]);
            CPASYNC16(st + ALO_OFF + a_sw[i], pal + a_go[i]);
            CPASYNC16(st + BHI_OFF + b_sw[i], pbh + b_go[i]);
            CPASYNC16(st + BLO_OFF + b_sw[i], pbl + b_go[i]);
        }
        CPCOMMIT();
    };

    float C[2][4][4];
#pragma unroll
    for (int i = 0; i < 2; i++)
#pragma unroll
        for (int j = 0; j < 4; j++)
#pragma unroll
            for (int q = 0; q < 4; q++) C[i][j][q] = 0.f;

    constexpr int CHUNKS = KDIM / 64;
    const int g  = lane >> 3;       // ldmatrix lane group
    const int lr = lane & 7;
    const int bhalf = wn >> 1;      // B smem half (cols 0-63 / 64-127)

    issue(0);
    for (int c = 0; c < CHUNKS; c++) {
        if (c + 1 < CHUNKS) { issue(c + 1); CPWAIT1(); }
        else                { CPWAIT0(); }
        __syncthreads();
        uint32_t st = sb + (c & 1) * STAGE_BYTES;

#pragma unroll
        for (int ks = 0; ks < 4; ks++) {
            uint32_t a[2][2][4];    // [mtile][plane][4]
#pragma unroll
            for (int mt = 0; mt < 2; mt++) {
                int row = wm * 32 + mt * 16 + (g & 1) * 8 + lr;
                int col = ks * 16 + (g >> 1) * 8;
                uint32_t off = SW128(row * 128 + col * 2);
                ldsm_x4(a[mt][0], st + AHI_OFF + off);
                ldsm_x4(a[mt][1], st + ALO_OFF + off);
            }
            uint32_t b[2][2][4];    // [n16][plane][4] = 2 n8 frags each
#pragma unroll
            for (int nt = 0; nt < 2; nt++) {
                int kk = ks * 16 + (g & 1) * 8 + lr;
                int nn = (wn & 1) * 32 + nt * 16 + (g >> 1) * 8;
                uint32_t off = bhalf * 8192 + SW128(kk * 128 + nn * 2);
                ldsm_x4_t(b[nt][0], st + BHI_OFF + off);
                ldsm_x4_t(b[nt][1], st + BLO_OFF + off);
            }
            // combos: hi*hi, hi*lo, lo*hi (combo-outer for accumulator ILP)
#pragma unroll
            for (int q = 0; q < 3; q++) {
                const int ap = (q == 2) ? 1 : 0;
                const int bp = (q == 1) ? 1 : 0;
#pragma unroll
                for (int mt = 0; mt < 2; mt++)
#pragma unroll
                    for (int nt = 0; nt < 2; nt++)
#pragma unroll
                        for (int s = 0; s < 2; s++)
                            mma16816(C[mt][nt * 2 + s], a[mt][ap],
                                     b[nt][bp][s * 2], b[nt][bp][s * 2 + 1]);
            }
        }
        __syncthreads();
    }

    // -------- epilogue
    const int qr = lane >> 2, qc = lane & 3;
#pragma unroll
    for (int mt = 0; mt < 2; mt++) {
#pragma unroll
        for (int j = 0; j < 4; j++) {
            int col = n0 + wn * 32 + j * 8 + qc * 2;
            float b0 = bias[e * NDIM + col];
            float b1 = bias[e * NDIM + col + 1];
#pragma unroll
            for (int h = 0; h < 2; h++) {
                int lrow = wm * 32 + mt * 16 + qr + h * 8;
                if (m0 + lrow >= cnt) continue;
                int gr = base + m0 + lrow;
                float v0 = C[mt][j][h * 2 + 0] + b0;
                float v1 = C[mt][j][h * 2 + 1] + b1;
                if (RELU) {
                    v0 = v0 > 0.f ? v0 : 0.f;
                    v1 = v1 > 0.f ? v1 : 0.f;
                    uint32_t lo2;
                    uint32_t hi2 = pack2(v0, v1, lo2);
                    size_t o = ((size_t)gr * NDIM + col) >> 1;
                    ((uint32_t*)Chi)[o] = hi2;
                    ((uint32_t*)Clo)[o] = lo2;
                } else {
                    float gate = g_rowgate[gr];
                    float2 o2 = make_float2(gate * v0, gate * v1);
                    *(float2*)(Cf + (size_t)gr * NDIM + col) = o2;
                }
            }
        }
    }
}

// -------------------- combine ----------------------------------------------
__global__ void combine_kernel(float* __restrict__ out, int T) {
    int i = blockIdx.x * blockDim.x + threadIdx.x;
    if (i >= T * D_DIM) return;
    int t = i >> 10;
    int d = i & (D_DIM - 1);
    out[i] = g_y[(size_t)g_slot[t * 2] * D_DIM + d] +
             g_y[(size_t)g_slot[t * 2 + 1] * D_DIM + d];
}

// -------------------- launch ------------------------------------------------
extern "C" void kernel_launch(void* const* d_in, const int* in_sizes, int n_in,
                              void* d_out, int out_size) {
    const float* x  = (const float*)d_in[0];
    const float* Wn = (const float*)d_in[1];
    const float* bn = (const float*)d_in[2];
    const float* W1 = (const float*)d_in[3];
    const float* b1 = (const float*)d_in[4];
    const float* W2 = (const float*)d_in[5];
    const float* b2 = (const float*)d_in[6];
    const int T = in_sizes[0] / D_DIM;

    cudaFuncSetAttribute(moe_gemm_kernel<D_DIM, F_DIM, true>,
                         cudaFuncAttributeMaxDynamicSharedMemorySize, SMEM_DYN);
    cudaFuncSetAttribute(moe_gemm_kernel<F_DIM, D_DIM, false>,
                         cudaFuncAttributeMaxDynamicSharedMemorySize, SMEM_DYN);

    __nv_bfloat16 *w1h, *w1l, *w2h, *w2l, *xh, *xl, *hh, *hl;
    float* yptr;
    cudaGetSymbolAddress((void**)&w1h, g_w1h);
    cudaGetSymbolAddress((void**)&w1l, g_w1l);
    cudaGetSymbolAddress((void**)&w2h, g_w2h);
    cudaGetSymbolAddress((void**)&w2l, g_w2l);
    cudaGetSymbolAddress((void**)&xh, g_xh);
    cudaGetSymbolAddress((void**)&xl, g_xl);
    cudaGetSymbolAddress((void**)&hh, g_hh);
    cudaGetSymbolAddress((void**)&hl, g_hl);
    cudaGetSymbolAddress((void**)&yptr, g_y);

    zero_cnt_kernel<<<1, 32>>>();
    router_kernel<<<(T * 32 + 255) / 256, 256>>>(x, Wn, bn, T);
    scan_kernel<<<1, 32>>>();
    build_kernel<<<(T * 2 + 255) / 256, 256>>>(T);
    gatherx_kernel<<<T * 2, 256>>>(x);

    const size_t wn4 = (size_t)E_NUM * D_DIM * F_DIM / 4;
    convert_kernel<<<(unsigned)((wn4 + 255) / 256), 256>>>(W1, w1h, w1l, wn4);
    convert_kernel<<<(unsigned)((wn4 + 255) / 256), 256>>>(W2, w2h, w2l, wn4);

    const int MT = (MAXT + 127) / 128;  // worst case: one expert takes all tokens
    dim3 g1(F_DIM / 128, MT, E_NUM);
    moe_gemm_kernel<D_DIM, F_DIM, true><<<g1, 512, SMEM_DYN>>>(
        xh, xl, w1h, w1l, b1, hh, hl, nullptr);
    dim3 g2(D_DIM / 128, MT, E_NUM);
    moe_gemm_kernel<F_DIM, D_DIM, false><<<g2, 512, SMEM_DYN>>>(
        hh, hl, w2h, w2l, b2, nullptr, nullptr, yptr);

    combine_kernel<<<(T * D_DIM + 255) / 256, 256>>>((float*)d_out, T);
}